// round 2
// baseline (speedup 1.0000x reference)
#include <cuda_runtime.h>

#define DM   1024
#define NH   16
#define HD   64
#define BATCH 2
#define SEQ  2048
#define MTOK (BATCH*SEQ)   // 4096

// Scratch (allocation-free rule: __device__ globals)
static __device__ float g_q[MTOK*DM];
static __device__ float g_k[MTOK*DM];
static __device__ float g_v[MTOK*DM];
static __device__ float g_att[MTOK*DM];

// ---------------------------------------------------------------------------
// C = A @ W + bias.  A: [MTOK, DM] row-major, W: [DM, DM] row-major.
// SPLIT=1: write C in [B, H, S, Dh] layout (head-split) for the attention stage.
// 128x128 block tile, BK=8, 256 threads, 8x8 per thread.
// ---------------------------------------------------------------------------
template<int SPLIT>
__global__ void __launch_bounds__(256) gemm_bias_kernel(
    const float* __restrict__ A, const float* __restrict__ W,
    const float* __restrict__ bias, float* __restrict__ C)
{
    __shared__ float As[128][9];    // [row][k], pad 9 to dodge bank conflicts
    __shared__ float Bs[8][128];    // [k][col]

    const int tid = threadIdx.x;
    const int br  = blockIdx.y * 128;
    const int bc  = blockIdx.x * 128;
    const int tr  = (tid >> 4) * 8;     // 0..120
    const int tc  = (tid & 15) * 8;     // 0..120

    float acc[8][8];
    #pragma unroll
    for (int i = 0; i < 8; i++)
        #pragma unroll
        for (int j = 0; j < 8; j++) acc[i][j] = 0.f;

    const int ar   = tid >> 1;          // 0..127  (A tile row)
    const int ak   = (tid & 1) * 4;     // 0 or 4  (A tile k chunk)
    const int brow = tid >> 5;          // 0..7    (B tile k row)
    const int bcol = (tid & 31) * 4;    // 0..124  (B tile col chunk)

    for (int k0 = 0; k0 < DM; k0 += 8) {
        float4 av = *(const float4*)&A[(size_t)(br + ar) * DM + k0 + ak];
        float4 bv = *(const float4*)&W[(size_t)(k0 + brow) * DM + bc + bcol];
        __syncthreads();   // previous iteration's compute done before overwrite
        As[ar][ak+0] = av.x; As[ar][ak+1] = av.y;
        As[ar][ak+2] = av.z; As[ar][ak+3] = av.w;
        *(float4*)&Bs[brow][bcol] = bv;
        __syncthreads();

        #pragma unroll
        for (int k = 0; k < 8; k++) {
            float a[8], b[8];
            #pragma unroll
            for (int i = 0; i < 8; i++) a[i] = As[tr + i][k];   // broadcast LDS
            float4 b0 = *(const float4*)&Bs[k][tc];
            float4 b1 = *(const float4*)&Bs[k][tc + 4];
            b[0]=b0.x; b[1]=b0.y; b[2]=b0.z; b[3]=b0.w;
            b[4]=b1.x; b[5]=b1.y; b[6]=b1.z; b[7]=b1.w;
            #pragma unroll
            for (int i = 0; i < 8; i++)
                #pragma unroll
                for (int j = 0; j < 8; j++)
                    acc[i][j] = fmaf(a[i], b[j], acc[i][j]);
        }
    }

    #pragma unroll
    for (int i = 0; i < 8; i++) {
        const int m = br + tr + i;
        #pragma unroll
        for (int j = 0; j < 8; j++) {
            const int n   = bc + tc + j;
            float val = acc[i][j] + bias[n];
            if (SPLIT) {
                const int b_ = m >> 11;            // m / SEQ
                const int s  = m & (SEQ - 1);
                const int h  = n >> 6;             // n / HD
                const int d  = n & (HD - 1);
                g_dummy_use:
                C[((((size_t)b_ * NH + h) * SEQ) + s) * HD + d] = val;
            } else {
                C[(size_t)m * DM + n] = val;
            }
        }
    }
}

// ---------------------------------------------------------------------------
// Flash attention, fp32.  q/k/v in [B,H,S,Dh].  Out written back to [B,S,D].
// Block: 64 queries for one (b,h); 256 threads (8 warps), warp owns 8 rows.
// Key tiles of 32.  scale = 1/sqrt(64) = 0.125.
// ---------------------------------------------------------------------------
__global__ void __launch_bounds__(256) attn_kernel(
    const float* __restrict__ q, const float* __restrict__ k,
    const float* __restrict__ v, float* __restrict__ out)
{
    __shared__ float q_t[64][64];   // TRANSPOSED: [d][r] -> float4 broadcast reads
    __shared__ float k_s[32][65];   // [key][d], pad 65: conflict-free col reads
    __shared__ float v_s[32][64];   // [key][d]
    __shared__ float p_s[64][36];   // [row][key], pad 36 keeps float4 alignment

    const int tid  = threadIdx.x;
    const int lane = tid & 31;
    const int warp = tid >> 5;
    const int r0   = warp * 8;
    const int bh   = blockIdx.y;            // b*NH + h
    const int q0   = blockIdx.x * 64;
    const float* __restrict__ qb = q + (size_t)bh * SEQ * HD;
    const float* __restrict__ kb = k + (size_t)bh * SEQ * HD;
    const float* __restrict__ vb = v + (size_t)bh * SEQ * HD;

    // Load Q tile transposed. Strided gmem reads; sectors reused 8x via L1.
    #pragma unroll
    for (int l = 0; l < 16; l++) {
        int e = tid + l * 256;
        int d = e >> 6, r = e & 63;
        q_t[d][r] = qb[(size_t)(q0 + r) * HD + d];
    }

    float m_i[8], l_i[8], O0[8], O1[8];
    #pragma unroll
    for (int i = 0; i < 8; i++) { m_i[i] = -1e30f; l_i[i] = 0.f; O0[i] = 0.f; O1[i] = 0.f; }

    for (int c0 = 0; c0 < SEQ; c0 += 32) {
        __syncthreads();
        #pragma unroll
        for (int l = 0; l < 8; l++) {
            int e = tid + l * 256;
            int r = e >> 6, c = e & 63;
            k_s[r][c] = kb[(size_t)(c0 + r) * HD + c];
            v_s[r][c] = vb[(size_t)(c0 + r) * HD + c];
        }
        __syncthreads();

        // scores: lane = key column, 8 rows per lane
        float acc[8];
        #pragma unroll
        for (int i = 0; i < 8; i++) acc[i] = 0.f;
        #pragma unroll 8
        for (int d = 0; d < HD; d++) {
            float kv  = k_s[lane][d];                        // conflict-free
            float4 qa = *(const float4*)&q_t[d][r0];         // broadcast
            float4 qc = *(const float4*)&q_t[d][r0 + 4];     // broadcast
            acc[0] = fmaf(qa.x, kv, acc[0]);
            acc[1] = fmaf(qa.y, kv, acc[1]);
            acc[2] = fmaf(qa.z, kv, acc[2]);
            acc[3] = fmaf(qa.w, kv, acc[3]);
            acc[4] = fmaf(qc.x, kv, acc[4]);
            acc[5] = fmaf(qc.y, kv, acc[5]);
            acc[6] = fmaf(qc.z, kv, acc[6]);
            acc[7] = fmaf(qc.w, kv, acc[7]);
        }

        // online softmax (warp-local: warp owns its 8 rows)
        #pragma unroll
        for (int i = 0; i < 8; i++) {
            float sc = acc[i] * 0.125f;
            float rm = sc;
            #pragma unroll
            for (int off = 16; off; off >>= 1)
                rm = fmaxf(rm, __shfl_xor_sync(0xffffffffu, rm, off));
            float mn    = fmaxf(m_i[i], rm);
            float alpha = __expf(m_i[i] - mn);
            float p     = __expf(sc - mn);
            float rs    = p;
            #pragma unroll
            for (int off = 16; off; off >>= 1)
                rs += __shfl_xor_sync(0xffffffffu, rs, off);
            l_i[i] = l_i[i] * alpha + rs;
            m_i[i] = mn;
            O0[i] *= alpha; O1[i] *= alpha;
            p_s[r0 + i][lane] = p;
        }
        __syncwarp();

        // O += P @ V.  lane owns dims {lane, lane+32} for its warp's 8 rows.
        #pragma unroll
        for (int c4 = 0; c4 < 8; c4++) {
            float v0[4], v1[4];
            #pragma unroll
            for (int u = 0; u < 4; u++) {
                v0[u] = v_s[c4 * 4 + u][lane];
                v1[u] = v_s[c4 * 4 + u][lane + 32];
            }
            #pragma unroll
            for (int i = 0; i < 8; i++) {
                float4 p4 = *(const float4*)&p_s[r0 + i][c4 * 4];  // broadcast
                O0[i] = fmaf(p4.x, v0[0], O0[i]);
                O1[i] = fmaf(p4.x, v1[0], O1[i]);
                O0[i] = fmaf(p4.y, v0[1], O0[i]);
                O1[i] = fmaf(p4.y, v1[1], O1[i]);
                O0[i] = fmaf(p4.z, v0[2], O0[i]);
                O1[i] = fmaf(p4.z, v1[2], O1[i]);
                O0[i] = fmaf(p4.w, v0[3], O0[i]);
                O1[i] = fmaf(p4.w, v1[3], O1[i]);
            }
        }
    }

    // epilogue: normalize and write back in [B, S, D] layout (merge heads)
    const int b_ = bh >> 4, h = bh & 15;
    #pragma unroll
    for (int i = 0; i < 8; i++) {
        float inv = __frcp_rn(l_i[i]);
        size_t base = ((size_t)(b_ * SEQ + q0 + r0 + i)) * DM + h * HD;
        out[base + lane]      = O0[i] * inv;
        out[base + lane + 32] = O1[i] * inv;
    }
}

// ---------------------------------------------------------------------------
extern "C" void kernel_launch(void* const* d_in, const int* in_sizes, int n_in,
                              void* d_out, int out_size)
{
    const float* Q  = (const float*)d_in[0];
    const float* K  = (const float*)d_in[1];
    const float* V  = (const float*)d_in[2];
    const float* Wq = (const float*)d_in[3];
    const float* bq = (const float*)d_in[4];
    const float* Wk = (const float*)d_in[5];
    const float* bk = (const float*)d_in[6];
    const float* Wv = (const float*)d_in[7];
    const float* bv = (const float*)d_in[8];
    const float* Wo = (const float*)d_in[9];
    const float* bo = (const float*)d_in[10];
    float* out = (float*)d_out;

    float *gq, *gk, *gv, *ga;
    cudaGetSymbolAddress((void**)&gq, g_q);
    cudaGetSymbolAddress((void**)&gk, g_k);
    cudaGetSymbolAddress((void**)&gv, g_v);
    cudaGetSymbolAddress((void**)&ga, g_att);

    dim3 gridP(DM / 128, MTOK / 128);       // (8, 32)
    gemm_bias_kernel<1><<<gridP, 256>>>(Q, Wq, bq, gq);
    gemm_bias_kernel<1><<<gridP, 256>>>(K, Wk, bk, gk);
    gemm_bias_kernel<1><<<gridP, 256>>>(V, Wv, bv, gv);

    dim3 gridA(SEQ / 64, BATCH * NH);       // (32, 32)
    attn_kernel<<<gridA, 256>>>(gq, gk, gv, ga);

    gemm_bias_kernel<0><<<gridP, 256>>>(ga, Wo, bo, out);
}

// round 6
// speedup vs baseline: 1.5317x; 1.5317x over previous
#include <cuda_runtime.h>
#include <cuda_bf16.h>
#include <cstdint>

#define DM   1024
#define NH   16
#define HD   64
#define BATCH 2
#define SEQ  2048
#define MTOK (BATCH*SEQ)   // 4096

// ---------------------------------------------------------------------------
// Scratch (allocation-free rule: __device__ globals)
// ---------------------------------------------------------------------------
static __device__ float g_q[MTOK*DM];
static __device__ float g_k[MTOK*DM];
static __device__ float g_v[MTOK*DM];
static __device__ float g_att[MTOK*DM];
static __device__ __nv_bfloat16 g_ah[MTOK*DM];   // activation split hi
static __device__ __nv_bfloat16 g_al[MTOK*DM];   // activation split lo
static __device__ __nv_bfloat16 g_wh[DM*DM];     // W^T split hi  [N,K]
static __device__ __nv_bfloat16 g_wl[DM*DM];     // W^T split lo  [N,K]

// ---------------------------------------------------------------------------
// helpers (arch-generic PTX only: ldmatrix / mma.sync / cp.async)
// ---------------------------------------------------------------------------
__device__ __forceinline__ uint32_t smem_u32(const void* p) {
    uint32_t a;
    asm("{ .reg .u64 t; cvta.to.shared.u64 t, %1; cvt.u32.u64 %0, t; }"
        : "=r"(a) : "l"(p));
    return a;
}

__device__ __forceinline__ void ldm_x4(uint32_t* r, uint32_t addr) {
    asm volatile("ldmatrix.sync.aligned.m8n8.x4.shared.b16 {%0,%1,%2,%3}, [%4];"
                 : "=r"(r[0]), "=r"(r[1]), "=r"(r[2]), "=r"(r[3]) : "r"(addr));
}

__device__ __forceinline__ void mma_bf16(float* d, const uint32_t* a,
                                         const uint32_t* b) {
    asm volatile(
        "mma.sync.aligned.m16n8k16.row.col.f32.bf16.bf16.f32 "
        "{%0,%1,%2,%3}, {%4,%5,%6,%7}, {%8,%9}, {%0,%1,%2,%3};"
        : "+f"(d[0]), "+f"(d[1]), "+f"(d[2]), "+f"(d[3])
        : "r"(a[0]), "r"(a[1]), "r"(a[2]), "r"(a[3]), "r"(b[0]), "r"(b[1]));
}

__device__ __forceinline__ void cp16(uint32_t dst, const void* src) {
    asm volatile("cp.async.cg.shared.global [%0], [%1], 16;"
                 :: "r"(dst), "l"(src));
}
#define CP_COMMIT() asm volatile("cp.async.commit_group;" ::: "memory")
#define CP_WAIT(n)  asm volatile("cp.async.wait_group %0;" :: "n"(n) : "memory")

// ---------------------------------------------------------------------------
// Split fp32 activation -> bf16 hi/lo arrays (same [M,K] layout)
// ---------------------------------------------------------------------------
__global__ void __launch_bounds__(256) split_act_kernel(
    const float* __restrict__ x,
    __nv_bfloat16* __restrict__ xh, __nv_bfloat16* __restrict__ xl)
{
    int i = blockIdx.x * blockDim.x + threadIdx.x;   // float4 index
    float4 v = ((const float4*)x)[i];
    float a[4] = {v.x, v.y, v.z, v.w};
    __nv_bfloat162 h01, h23, l01, l23;
    __nv_bfloat16 h0 = __float2bfloat16(a[0]);
    __nv_bfloat16 h1 = __float2bfloat16(a[1]);
    __nv_bfloat16 h2 = __float2bfloat16(a[2]);
    __nv_bfloat16 h3 = __float2bfloat16(a[3]);
    h01.x = h0; h01.y = h1; h23.x = h2; h23.y = h3;
    l01.x = __float2bfloat16(a[0] - __bfloat162float(h0));
    l01.y = __float2bfloat16(a[1] - __bfloat162float(h1));
    l23.x = __float2bfloat16(a[2] - __bfloat162float(h2));
    l23.y = __float2bfloat16(a[3] - __bfloat162float(h3));
    ((__nv_bfloat162*)xh)[2*i]   = h01;
    ((__nv_bfloat162*)xh)[2*i+1] = h23;
    ((__nv_bfloat162*)xl)[2*i]   = l01;
    ((__nv_bfloat162*)xl)[2*i+1] = l23;
}

// ---------------------------------------------------------------------------
// Transpose + split weight:  W[k][n] fp32 -> wh/wl[n][k] bf16
// ---------------------------------------------------------------------------
__global__ void __launch_bounds__(256) trans_split_kernel(
    const float* __restrict__ W,
    __nv_bfloat16* __restrict__ wh, __nv_bfloat16* __restrict__ wl)
{
    __shared__ float t[32][33];
    const int k0 = blockIdx.y * 32, n0 = blockIdx.x * 32;
    const int tx = threadIdx.x, ty = threadIdx.y;     // (32, 8)
    #pragma unroll
    for (int j = 0; j < 4; j++)
        t[ty + j*8][tx] = W[(size_t)(k0 + ty + j*8) * DM + n0 + tx];
    __syncthreads();
    #pragma unroll
    for (int j = 0; j < 4; j++) {
        int nn = ty + j*8;
        float v = t[tx][nn];                           // = W[k0+tx][n0+nn]
        __nv_bfloat16 h = __float2bfloat16(v);
        size_t idx = (size_t)(n0 + nn) * DM + k0 + tx;
        wh[idx] = h;
        wl[idx] = __float2bfloat16(v - __bfloat162float(h));
    }
}

// ---------------------------------------------------------------------------
// Tensor-core split-bf16 GEMM via mma.sync (HMMA):
//   C[M,N] = A@W + bias,  D = Ah*Bh + Ah*Bl + Al*Bh (fp32 accum)
// CTA 128x128, K-chunk 32, 8 warps (2m x 4n), warp tile 64x32.
// cp.async double-buffered smem, stride 40 bf16:
//   ldmatrix row word-offsets 20r mod 32 cover all banks -> conflict-free.
// 80KB smem/CTA -> 2 CTAs/SM (latency hiding across sync boundaries).
// SPLIT=1 writes C in [B,H,S,Dh] layout.
// ---------------------------------------------------------------------------
#define BM 128
#define BN 128
#define BK 32
#define STR 40
#define TILE_ELEMS (BM * STR)                 // per tensor, bf16
#define STAGE_ELEMS (4 * TILE_ELEMS)          // Ah,Al,Bh,Bl
#define GEMM_SMEM (2 * STAGE_ELEMS * 2)       // bytes (2 stages) = 81920
#define NCHUNK (DM / BK)                      // 32

template<int SPLIT>
__global__ void __launch_bounds__(256) gemm_mma_kernel(
    const __nv_bfloat16* __restrict__ Ah, const __nv_bfloat16* __restrict__ Al,
    const __nv_bfloat16* __restrict__ Bh, const __nv_bfloat16* __restrict__ Bl,
    const float* __restrict__ bias, float* __restrict__ C)
{
    extern __shared__ __nv_bfloat16 sm[];
    const uint32_t sbase = smem_u32(sm);

    const int tid  = threadIdx.x;
    const int lane = tid & 31;
    const int wid  = tid >> 5;
    const int wm   = (wid >> 2) * 64;         // warp m offset in tile
    const int wn   = (wid & 3) * 32;          // warp n offset in tile
    const int bm   = blockIdx.y * BM;
    const int bn   = blockIdx.x * BN;

    float acc[4][4][4];
    #pragma unroll
    for (int i = 0; i < 4; i++)
        #pragma unroll
        for (int j = 0; j < 4; j++)
            #pragma unroll
            for (int c = 0; c < 4; c++) acc[i][j][c] = 0.f;

    // ldmatrix per-thread base offsets (bf16 elements)
    const int a_r  = wm + (lane & 7) + ((lane >> 3) & 1) * 8;
    const int a_k  = (lane >> 4) * 8;
    const int b_r  = wn + (lane & 7) + (lane >> 4) * 8;
    const int b_k  = ((lane >> 3) & 1) * 8;

    // gmem->smem: per tensor 128 rows x 4 uint4 = 512 uint4, 2 per thread
    auto issue_chunk = [&](int c, int stg) {
        const int k0 = c * BK;
        const uint32_t sA = sbase + (uint32_t)(stg * STAGE_ELEMS) * 2;
        #pragma unroll
        for (int i = 0; i < 2; i++) {
            int t = tid + i * 256;
            int r = t >> 2, cc = (t & 3) * 8;
            uint32_t so = (uint32_t)(r * STR + cc) * 2;
            size_t ga = (size_t)(bm + r) * DM + k0 + cc;
            size_t gb = (size_t)(bn + r) * DM + k0 + cc;
            cp16(sA + so,                      Ah + ga);
            cp16(sA + TILE_ELEMS*2 + so,       Al + ga);
            cp16(sA + 2*TILE_ELEMS*2 + so,     Bh + gb);
            cp16(sA + 3*TILE_ELEMS*2 + so,     Bl + gb);
        }
        CP_COMMIT();
    };

    issue_chunk(0, 0);

    for (int c = 0; c < NCHUNK; c++) {
        if (c + 1 < NCHUNK) {
            issue_chunk(c + 1, (c + 1) & 1);
            CP_WAIT(1);
        } else {
            CP_WAIT(0);
        }
        __syncthreads();

        const uint32_t sA  = sbase + (uint32_t)((c & 1) * STAGE_ELEMS) * 2;
        const uint32_t sAl = sA + TILE_ELEMS * 2;
        const uint32_t sB  = sA + 2 * TILE_ELEMS * 2;
        const uint32_t sBl = sA + 3 * TILE_ELEMS * 2;

        #pragma unroll
        for (int ks = 0; ks < BK / 16; ks++) {
            uint32_t ra[4][4], rbh[2][4], rbl[2][4];
            #pragma unroll
            for (int mi = 0; mi < 4; mi++)
                ldm_x4(ra[mi], sA + (uint32_t)((a_r + mi*16) * STR + ks*16 + a_k) * 2);
            #pragma unroll
            for (int n2 = 0; n2 < 2; n2++) {
                ldm_x4(rbh[n2], sB  + (uint32_t)((b_r + n2*16) * STR + ks*16 + b_k) * 2);
                ldm_x4(rbl[n2], sBl + (uint32_t)((b_r + n2*16) * STR + ks*16 + b_k) * 2);
            }
            // pass 1: Ah x Bh ; pass 2: Ah x Bl
            #pragma unroll
            for (int mi = 0; mi < 4; mi++)
                #pragma unroll
                for (int ni = 0; ni < 4; ni++)
                    mma_bf16(acc[mi][ni], ra[mi], &rbh[ni >> 1][(ni & 1) * 2]);
            #pragma unroll
            for (int mi = 0; mi < 4; mi++)
                #pragma unroll
                for (int ni = 0; ni < 4; ni++)
                    mma_bf16(acc[mi][ni], ra[mi], &rbl[ni >> 1][(ni & 1) * 2]);
            // pass 3: Al x Bh (reload A frags as Al)
            #pragma unroll
            for (int mi = 0; mi < 4; mi++)
                ldm_x4(ra[mi], sAl + (uint32_t)((a_r + mi*16) * STR + ks*16 + a_k) * 2);
            #pragma unroll
            for (int mi = 0; mi < 4; mi++)
                #pragma unroll
                for (int ni = 0; ni < 4; ni++)
                    mma_bf16(acc[mi][ni], ra[mi], &rbh[ni >> 1][(ni & 1) * 2]);
        }
        __syncthreads();   // stage consumed; safe for next cp.async overwrite
    }

    // epilogue: c0,c1 -> (row, col..col+1); c2,c3 -> (row+8, ...)
    const int er = lane >> 2;
    const int ec = (lane & 3) * 2;
    #pragma unroll
    for (int mi = 0; mi < 4; mi++) {
        #pragma unroll
        for (int ni = 0; ni < 4; ni++) {
            const int n  = bn + wn + ni * 8 + ec;
            const float b0 = bias[n], b1 = bias[n + 1];
            #pragma unroll
            for (int half = 0; half < 2; half++) {
                const int m = bm + wm + mi * 16 + er + half * 8;
                float2 o;
                o.x = acc[mi][ni][half * 2 + 0] + b0;
                o.y = acc[mi][ni][half * 2 + 1] + b1;
                if (SPLIT) {
                    const int b_ = m >> 11;
                    const int s  = m & (SEQ - 1);
                    const int h  = n >> 6;
                    const int d  = n & (HD - 1);
                    *(float2*)&C[((((size_t)b_ * NH + h) * SEQ) + s) * HD + d] = o;
                } else {
                    *(float2*)&C[(size_t)m * DM + n] = o;
                }
            }
        }
    }
}

// ---------------------------------------------------------------------------
// Flash attention, fp32 (unchanged from R1 — known correct; next target).
// ---------------------------------------------------------------------------
__global__ void __launch_bounds__(256) attn_kernel(
    const float* __restrict__ q, const float* __restrict__ k,
    const float* __restrict__ v, float* __restrict__ out)
{
    __shared__ float q_t[64][64];
    __shared__ float k_s[32][65];
    __shared__ float v_s[32][64];
    __shared__ float p_s[64][36];

    const int tid  = threadIdx.x;
    const int lane = tid & 31;
    const int warp = tid >> 5;
    const int r0   = warp * 8;
    const int bh   = blockIdx.y;
    const int q0   = blockIdx.x * 64;
    const float* __restrict__ qb = q + (size_t)bh * SEQ * HD;
    const float* __restrict__ kb = k + (size_t)bh * SEQ * HD;
    const float* __restrict__ vb = v + (size_t)bh * SEQ * HD;

    #pragma unroll
    for (int l = 0; l < 16; l++) {
        int e = tid + l * 256;
        int d = e >> 6, r = e & 63;
        q_t[d][r] = qb[(size_t)(q0 + r) * HD + d];
    }

    float m_i[8], l_i[8], O0[8], O1[8];
    #pragma unroll
    for (int i = 0; i < 8; i++) { m_i[i] = -1e30f; l_i[i] = 0.f; O0[i] = 0.f; O1[i] = 0.f; }

    for (int c0 = 0; c0 < SEQ; c0 += 32) {
        __syncthreads();
        #pragma unroll
        for (int l = 0; l < 8; l++) {
            int e = tid + l * 256;
            int r = e >> 6, c = e & 63;
            k_s[r][c] = kb[(size_t)(c0 + r) * HD + c];
            v_s[r][c] = vb[(size_t)(c0 + r) * HD + c];
        }
        __syncthreads();

        float acc[8];
        #pragma unroll
        for (int i = 0; i < 8; i++) acc[i] = 0.f;
        #pragma unroll 8
        for (int d = 0; d < HD; d++) {
            float kv  = k_s[lane][d];
            float4 qa = *(const float4*)&q_t[d][r0];
            float4 qc = *(const float4*)&q_t[d][r0 + 4];
            acc[0] = fmaf(qa.x, kv, acc[0]);
            acc[1] = fmaf(qa.y, kv, acc[1]);
            acc[2] = fmaf(qa.z, kv, acc[2]);
            acc[3] = fmaf(qa.w, kv, acc[3]);
            acc[4] = fmaf(qc.x, kv, acc[4]);
            acc[5] = fmaf(qc.y, kv, acc[5]);
            acc[6] = fmaf(qc.z, kv, acc[6]);
            acc[7] = fmaf(qc.w, kv, acc[7]);
        }

        #pragma unroll
        for (int i = 0; i < 8; i++) {
            float sc = acc[i] * 0.125f;
            float rm = sc;
            #pragma unroll
            for (int off = 16; off; off >>= 1)
                rm = fmaxf(rm, __shfl_xor_sync(0xffffffffu, rm, off));
            float mn    = fmaxf(m_i[i], rm);
            float alpha = __expf(m_i[i] - mn);
            float p     = __expf(sc - mn);
            float rs    = p;
            #pragma unroll
            for (int off = 16; off; off >>= 1)
                rs += __shfl_xor_sync(0xffffffffu, rs, off);
            l_i[i] = l_i[i] * alpha + rs;
            m_i[i] = mn;
            O0[i] *= alpha; O1[i] *= alpha;
            p_s[r0 + i][lane] = p;
        }
        __syncwarp();

        #pragma unroll
        for (int c4 = 0; c4 < 8; c4++) {
            float v0[4], v1[4];
            #pragma unroll
            for (int u = 0; u < 4; u++) {
                v0[u] = v_s[c4 * 4 + u][lane];
                v1[u] = v_s[c4 * 4 + u][lane + 32];
            }
            #pragma unroll
            for (int i = 0; i < 8; i++) {
                float4 p4 = *(const float4*)&p_s[r0 + i][c4 * 4];
                O0[i] = fmaf(p4.x, v0[0], O0[i]);
                O1[i] = fmaf(p4.x, v1[0], O1[i]);
                O0[i] = fmaf(p4.y, v0[1], O0[i]);
                O1[i] = fmaf(p4.y, v1[1], O1[i]);
                O0[i] = fmaf(p4.z, v0[2], O0[i]);
                O1[i] = fmaf(p4.z, v1[2], O1[i]);
                O0[i] = fmaf(p4.w, v0[3], O0[i]);
                O1[i] = fmaf(p4.w, v1[3], O1[i]);
            }
        }
    }

    const int b_ = bh >> 4, h = bh & 15;
    #pragma unroll
    for (int i = 0; i < 8; i++) {
        float inv = __frcp_rn(l_i[i]);
        size_t base = ((size_t)(b_ * SEQ + q0 + r0 + i)) * DM + h * HD;
        out[base + lane]      = O0[i] * inv;
        out[base + lane + 32] = O1[i] * inv;
    }
}

// ---------------------------------------------------------------------------
extern "C" void kernel_launch(void* const* d_in, const int* in_sizes, int n_in,
                              void* d_out, int out_size)
{
    const float* Q  = (const float*)d_in[0];
    const float* K  = (const float*)d_in[1];
    const float* V  = (const float*)d_in[2];
    const float* Wq = (const float*)d_in[3];
    const float* bq = (const float*)d_in[4];
    const float* Wk = (const float*)d_in[5];
    const float* bk = (const float*)d_in[6];
    const float* Wv = (const float*)d_in[7];
    const float* bv = (const float*)d_in[8];
    const float* Wo = (const float*)d_in[9];
    const float* bo = (const float*)d_in[10];
    float* out = (float*)d_out;

    float *gq, *gk, *gv, *ga;
    __nv_bfloat16 *ah, *al, *wh, *wl;
    cudaGetSymbolAddress((void**)&gq, g_q);
    cudaGetSymbolAddress((void**)&gk, g_k);
    cudaGetSymbolAddress((void**)&gv, g_v);
    cudaGetSymbolAddress((void**)&ga, g_att);
    cudaGetSymbolAddress((void**)&ah, g_ah);
    cudaGetSymbolAddress((void**)&al, g_al);
    cudaGetSymbolAddress((void**)&wh, g_wh);
    cudaGetSymbolAddress((void**)&wl, g_wl);

    cudaFuncSetAttribute(gemm_mma_kernel<0>,
                         cudaFuncAttributeMaxDynamicSharedMemorySize, GEMM_SMEM);
    cudaFuncSetAttribute(gemm_mma_kernel<1>,
                         cudaFuncAttributeMaxDynamicSharedMemorySize, GEMM_SMEM);

    const dim3 gridSplit(MTOK * DM / 4 / 256);        // 4096 blocks
    const dim3 gridTr(DM / 32, DM / 32), blkTr(32, 8);
    const dim3 gridG(DM / 128, MTOK / 128);           // (8, 32)

    // Q projection
    split_act_kernel<<<gridSplit, 256>>>(Q, ah, al);
    trans_split_kernel<<<gridTr, blkTr>>>(Wq, wh, wl);
    gemm_mma_kernel<1><<<gridG, 256, GEMM_SMEM>>>(ah, al, wh, wl, bq, gq);
    // K projection
    split_act_kernel<<<gridSplit, 256>>>(K, ah, al);
    trans_split_kernel<<<gridTr, blkTr>>>(Wk, wh, wl);
    gemm_mma_kernel<1><<<gridG, 256, GEMM_SMEM>>>(ah, al, wh, wl, bk, gk);
    // V projection
    split_act_kernel<<<gridSplit, 256>>>(V, ah, al);
    trans_split_kernel<<<gridTr, blkTr>>>(Wv, wh, wl);
    gemm_mma_kernel<1><<<gridG, 256, GEMM_SMEM>>>(ah, al, wh, wl, bv, gv);

    // attention
    const dim3 gridA(SEQ / 64, BATCH * NH);           // (32, 32)
    attn_kernel<<<gridA, 256>>>(gq, gk, gv, ga);

    // output projection
    split_act_kernel<<<gridSplit, 256>>>(ga, ah, al);
    trans_split_kernel<<<gridTr, blkTr>>>(Wo, wh, wl);
    gemm_mma_kernel<0><<<gridG, 256, GEMM_SMEM>>>(ah, al, wh, wl, bo, out);
}

// round 7
// speedup vs baseline: 3.4855x; 2.2756x over previous
#include <cuda_runtime.h>
#include <cuda_bf16.h>
#include <cstdint>

#define DM   1024
#define NH   16
#define HD   64
#define BATCH 2
#define SEQ  2048
#define MTOK (BATCH*SEQ)   // 4096

// ---------------------------------------------------------------------------
// Scratch (allocation-free rule: __device__ globals)
// ---------------------------------------------------------------------------
static __device__ __nv_bfloat16 g_ah[MTOK*DM];   // activation split hi / attn out hi
static __device__ __nv_bfloat16 g_al[MTOK*DM];   // activation split lo / attn out lo
static __device__ __nv_bfloat16 g_wh[DM*DM];     // W^T split hi  [N,K]
static __device__ __nv_bfloat16 g_wl[DM*DM];     // W^T split lo  [N,K]
static __device__ __nv_bfloat16 g_qh[MTOK*DM];   // q  [B,H,S,Dh]
static __device__ __nv_bfloat16 g_ql[MTOK*DM];
static __device__ __nv_bfloat16 g_kh[MTOK*DM];   // k  [B,H,S,Dh]
static __device__ __nv_bfloat16 g_kl[MTOK*DM];
static __device__ __nv_bfloat16 g_vh[MTOK*DM];   // v  [B,H,Dh,S] (transposed)
static __device__ __nv_bfloat16 g_vl[MTOK*DM];

// ---------------------------------------------------------------------------
// helpers (arch-generic PTX only: ldmatrix / mma.sync / cp.async)
// ---------------------------------------------------------------------------
__device__ __forceinline__ uint32_t smem_u32(const void* p) {
    uint32_t a;
    asm("{ .reg .u64 t; cvta.to.shared.u64 t, %1; cvt.u32.u64 %0, t; }"
        : "=r"(a) : "l"(p));
    return a;
}
__device__ __forceinline__ void ldm_x4(uint32_t* r, uint32_t addr) {
    asm volatile("ldmatrix.sync.aligned.m8n8.x4.shared.b16 {%0,%1,%2,%3}, [%4];"
                 : "=r"(r[0]), "=r"(r[1]), "=r"(r[2]), "=r"(r[3]) : "r"(addr));
}
__device__ __forceinline__ void mma_bf16(float* d, const uint32_t* a,
                                         const uint32_t* b) {
    asm volatile(
        "mma.sync.aligned.m16n8k16.row.col.f32.bf16.bf16.f32 "
        "{%0,%1,%2,%3}, {%4,%5,%6,%7}, {%8,%9}, {%0,%1,%2,%3};"
        : "+f"(d[0]), "+f"(d[1]), "+f"(d[2]), "+f"(d[3])
        : "r"(a[0]), "r"(a[1]), "r"(a[2]), "r"(a[3]), "r"(b[0]), "r"(b[1]));
}
__device__ __forceinline__ void cp16(uint32_t dst, const void* src) {
    asm volatile("cp.async.cg.shared.global [%0], [%1], 16;"
                 :: "r"(dst), "l"(src));
}
#define CP_COMMIT() asm volatile("cp.async.commit_group;" ::: "memory")
#define CP_WAIT(n)  asm volatile("cp.async.wait_group %0;" :: "n"(n) : "memory")

__device__ __forceinline__ uint32_t pack_bf16(float lo, float hi) {
    uint32_t r;
    asm("cvt.rn.bf16x2.f32 %0, %1, %2;" : "=r"(r) : "f"(hi), "f"(lo));
    return r;
}
__device__ __forceinline__ float bf16_round(float v) {
    return __bfloat162float(__float2bfloat16(v));
}

// ---------------------------------------------------------------------------
// Split fp32 activation -> bf16 hi/lo arrays (same [M,K] layout)
// ---------------------------------------------------------------------------
__global__ void __launch_bounds__(256) split_act_kernel(
    const float* __restrict__ x,
    __nv_bfloat16* __restrict__ xh, __nv_bfloat16* __restrict__ xl)
{
    int i = blockIdx.x * blockDim.x + threadIdx.x;   // float4 index
    float4 v = ((const float4*)x)[i];
    float a[4] = {v.x, v.y, v.z, v.w};
    __nv_bfloat162 h01, h23, l01, l23;
    __nv_bfloat16 h0 = __float2bfloat16(a[0]);
    __nv_bfloat16 h1 = __float2bfloat16(a[1]);
    __nv_bfloat16 h2 = __float2bfloat16(a[2]);
    __nv_bfloat16 h3 = __float2bfloat16(a[3]);
    h01.x = h0; h01.y = h1; h23.x = h2; h23.y = h3;
    l01.x = __float2bfloat16(a[0] - __bfloat162float(h0));
    l01.y = __float2bfloat16(a[1] - __bfloat162float(h1));
    l23.x = __float2bfloat16(a[2] - __bfloat162float(h2));
    l23.y = __float2bfloat16(a[3] - __bfloat162float(h3));
    ((__nv_bfloat162*)xh)[2*i]   = h01;
    ((__nv_bfloat162*)xh)[2*i+1] = h23;
    ((__nv_bfloat162*)xl)[2*i]   = l01;
    ((__nv_bfloat162*)xl)[2*i+1] = l23;
}

// ---------------------------------------------------------------------------
// Transpose + split weight:  W[k][n] fp32 -> wh/wl[n][k] bf16
// ---------------------------------------------------------------------------
__global__ void __launch_bounds__(256) trans_split_kernel(
    const float* __restrict__ W,
    __nv_bfloat16* __restrict__ wh, __nv_bfloat16* __restrict__ wl)
{
    __shared__ float t[32][33];
    const int k0 = blockIdx.y * 32, n0 = blockIdx.x * 32;
    const int tx = threadIdx.x, ty = threadIdx.y;     // (32, 8)
    #pragma unroll
    for (int j = 0; j < 4; j++)
        t[ty + j*8][tx] = W[(size_t)(k0 + ty + j*8) * DM + n0 + tx];
    __syncthreads();
    #pragma unroll
    for (int j = 0; j < 4; j++) {
        int nn = ty + j*8;
        float v = t[tx][nn];                           // = W[k0+tx][n0+nn]
        __nv_bfloat16 h = __float2bfloat16(v);
        size_t idx = (size_t)(n0 + nn) * DM + k0 + tx;
        wh[idx] = h;
        wl[idx] = __float2bfloat16(v - __bfloat162float(h));
    }
}

// ---------------------------------------------------------------------------
// Tensor-core split-bf16 GEMM via mma.sync (HMMA), from R5 (passing).
// MODE 0: fp32 out [M,DM].  MODE 1: split bf16 out [B,H,S,Dh].
// MODE 2: split bf16 out [B,H,Dh,S] (transposed, for V).
// ---------------------------------------------------------------------------
#define BM 128
#define BN 128
#define BK 32
#define STR 40
#define TILE_ELEMS (BM * STR)
#define STAGE_ELEMS (4 * TILE_ELEMS)
#define GEMM_SMEM (2 * STAGE_ELEMS * 2)       // 81920 B
#define NCHUNK (DM / BK)                      // 32

template<int MODE>
__global__ void __launch_bounds__(256) gemm_mma_kernel(
    const __nv_bfloat16* __restrict__ Ah, const __nv_bfloat16* __restrict__ Al,
    const __nv_bfloat16* __restrict__ Bh, const __nv_bfloat16* __restrict__ Bl,
    const float* __restrict__ bias, float* __restrict__ Cf,
    __nv_bfloat16* __restrict__ Ch, __nv_bfloat16* __restrict__ Cl)
{
    extern __shared__ __nv_bfloat16 sm[];
    const uint32_t sbase = smem_u32(sm);

    const int tid  = threadIdx.x;
    const int lane = tid & 31;
    const int wid  = tid >> 5;
    const int wm   = (wid >> 2) * 64;
    const int wn   = (wid & 3) * 32;
    const int bm   = blockIdx.y * BM;
    const int bn   = blockIdx.x * BN;

    float acc[4][4][4];
    #pragma unroll
    for (int i = 0; i < 4; i++)
        #pragma unroll
        for (int j = 0; j < 4; j++)
            #pragma unroll
            for (int c = 0; c < 4; c++) acc[i][j][c] = 0.f;

    const int a_r  = wm + (lane & 7) + ((lane >> 3) & 1) * 8;
    const int a_k  = (lane >> 4) * 8;
    const int b_r  = wn + (lane & 7) + (lane >> 4) * 8;
    const int b_k  = ((lane >> 3) & 1) * 8;

    auto issue_chunk = [&](int c, int stg) {
        const int k0 = c * BK;
        const uint32_t sA = sbase + (uint32_t)(stg * STAGE_ELEMS) * 2;
        #pragma unroll
        for (int i = 0; i < 2; i++) {
            int t = tid + i * 256;
            int r = t >> 2, cc = (t & 3) * 8;
            uint32_t so = (uint32_t)(r * STR + cc) * 2;
            size_t ga = (size_t)(bm + r) * DM + k0 + cc;
            size_t gb = (size_t)(bn + r) * DM + k0 + cc;
            cp16(sA + so,                      Ah + ga);
            cp16(sA + TILE_ELEMS*2 + so,       Al + ga);
            cp16(sA + 2*TILE_ELEMS*2 + so,     Bh + gb);
            cp16(sA + 3*TILE_ELEMS*2 + so,     Bl + gb);
        }
        CP_COMMIT();
    };

    issue_chunk(0, 0);

    for (int c = 0; c < NCHUNK; c++) {
        if (c + 1 < NCHUNK) {
            issue_chunk(c + 1, (c + 1) & 1);
            CP_WAIT(1);
        } else {
            CP_WAIT(0);
        }
        __syncthreads();

        const uint32_t sA  = sbase + (uint32_t)((c & 1) * STAGE_ELEMS) * 2;
        const uint32_t sAl = sA + TILE_ELEMS * 2;
        const uint32_t sB  = sA + 2 * TILE_ELEMS * 2;
        const uint32_t sBl = sA + 3 * TILE_ELEMS * 2;

        #pragma unroll
        for (int ks = 0; ks < BK / 16; ks++) {
            uint32_t ra[4][4], rbh[2][4], rbl[2][4];
            #pragma unroll
            for (int mi = 0; mi < 4; mi++)
                ldm_x4(ra[mi], sA + (uint32_t)((a_r + mi*16) * STR + ks*16 + a_k) * 2);
            #pragma unroll
            for (int n2 = 0; n2 < 2; n2++) {
                ldm_x4(rbh[n2], sB  + (uint32_t)((b_r + n2*16) * STR + ks*16 + b_k) * 2);
                ldm_x4(rbl[n2], sBl + (uint32_t)((b_r + n2*16) * STR + ks*16 + b_k) * 2);
            }
            #pragma unroll
            for (int mi = 0; mi < 4; mi++)
                #pragma unroll
                for (int ni = 0; ni < 4; ni++)
                    mma_bf16(acc[mi][ni], ra[mi], &rbh[ni >> 1][(ni & 1) * 2]);
            #pragma unroll
            for (int mi = 0; mi < 4; mi++)
                #pragma unroll
                for (int ni = 0; ni < 4; ni++)
                    mma_bf16(acc[mi][ni], ra[mi], &rbl[ni >> 1][(ni & 1) * 2]);
            #pragma unroll
            for (int mi = 0; mi < 4; mi++)
                ldm_x4(ra[mi], sAl + (uint32_t)((a_r + mi*16) * STR + ks*16 + a_k) * 2);
            #pragma unroll
            for (int mi = 0; mi < 4; mi++)
                #pragma unroll
                for (int ni = 0; ni < 4; ni++)
                    mma_bf16(acc[mi][ni], ra[mi], &rbh[ni >> 1][(ni & 1) * 2]);
        }
        __syncthreads();
    }

    const int er = lane >> 2;
    const int ec = (lane & 3) * 2;
    #pragma unroll
    for (int mi = 0; mi < 4; mi++) {
        #pragma unroll
        for (int ni = 0; ni < 4; ni++) {
            const int n  = bn + wn + ni * 8 + ec;
            const float b0 = bias[n], b1 = bias[n + 1];
            #pragma unroll
            for (int half = 0; half < 2; half++) {
                const int m = bm + wm + mi * 16 + er + half * 8;
                float v0 = acc[mi][ni][half * 2 + 0] + b0;
                float v1 = acc[mi][ni][half * 2 + 1] + b1;
                if (MODE == 0) {
                    float2 o; o.x = v0; o.y = v1;
                    *(float2*)&Cf[(size_t)m * DM + n] = o;
                } else {
                    float h0 = bf16_round(v0), h1 = bf16_round(v1);
                    const int b_ = m >> 11;
                    const int s  = m & (SEQ - 1);
                    const int h  = n >> 6;
                    const int d  = n & (HD - 1);
                    if (MODE == 1) {
                        size_t idx = ((((size_t)b_ * NH + h) * SEQ) + s) * HD + d;
                        *(uint32_t*)&Ch[idx] = pack_bf16(h0, h1);
                        *(uint32_t*)&Cl[idx] = pack_bf16(v0 - h0, v1 - h1);
                    } else {   // MODE 2: transposed [B,H,Dh,S]
                        size_t base = (((size_t)b_ * NH + h) * HD + d) * SEQ + s;
                        Ch[base]       = __float2bfloat16(h0);
                        Ch[base + SEQ] = __float2bfloat16(h1);
                        Cl[base]       = __float2bfloat16(v0 - h0);
                        Cl[base + SEQ] = __float2bfloat16(v1 - h1);
                    }
                }
            }
        }
    }
}

// ---------------------------------------------------------------------------
// Tensor-core flash attention, split bf16 (3-pass per GEMM).
// CTA: 64 queries of one (b,h); 128 thr / 4 warps; warp = 16 rows.
// k-tile 64, double-buffered cp.async. S-accum -> P A-frags in registers.
// Writes attn output as split bf16 in [B,S,DM] for the O projection.
// ---------------------------------------------------------------------------
#define ASTR 72
#define ATILE (64 * ASTR)                     // bf16 elems per tile
#define ATT_SMEM ((2 + 8) * ATILE * 2)        // Q(2) + 2 stages x 4 tiles = 92160 B

__global__ void __launch_bounds__(128) attn_mma_kernel(
    const __nv_bfloat16* __restrict__ qh, const __nv_bfloat16* __restrict__ ql,
    const __nv_bfloat16* __restrict__ kh, const __nv_bfloat16* __restrict__ kl,
    const __nv_bfloat16* __restrict__ vh, const __nv_bfloat16* __restrict__ vl,
    __nv_bfloat16* __restrict__ oh, __nv_bfloat16* __restrict__ ol)
{
    extern __shared__ __nv_bfloat16 smA[];
    const uint32_t sb  = smem_u32(smA);
    const int tid  = threadIdx.x;
    const int lane = tid & 31;
    const int w    = tid >> 5;
    const int bh   = blockIdx.y;              // b*NH + h
    const int q0   = blockIdx.x * 64;
    const size_t bo = (size_t)bh * SEQ * HD;  // == bh*HD*SEQ

    const uint32_t sQh = sb;
    const uint32_t sQl = sb + ATILE * 2;

    auto issue_stage = [&](int t, int stg) {
        const int c0 = t * 64;
        const uint32_t base = sb + (uint32_t)(2 + 4 * stg) * ATILE * 2;
        const __nv_bfloat16* gkh = kh + bo + (size_t)c0 * HD;
        const __nv_bfloat16* gkl = kl + bo + (size_t)c0 * HD;
        const __nv_bfloat16* gvh = vh + bo + c0;
        const __nv_bfloat16* gvl = vl + bo + c0;
        #pragma unroll
        for (int i = 0; i < 4; i++) {
            int e = tid + i * 128;
            int r = e >> 3, c8 = (e & 7) * 8;
            uint32_t so = (uint32_t)(r * ASTR + c8) * 2;
            cp16(base + so,               gkh + r * HD + c8);
            cp16(base + ATILE*2 + so,     gkl + r * HD + c8);
            cp16(base + 2*ATILE*2 + so,   gvh + (size_t)r * SEQ + c8);
            cp16(base + 3*ATILE*2 + so,   gvl + (size_t)r * SEQ + c8);
        }
        CP_COMMIT();
    };

    // Q tile (once) + stage 0, one cp.async group
    {
        const __nv_bfloat16* gqh = qh + bo + (size_t)q0 * HD;
        const __nv_bfloat16* gql = ql + bo + (size_t)q0 * HD;
        #pragma unroll
        for (int i = 0; i < 4; i++) {
            int e = tid + i * 128;
            int r = e >> 3, c8 = (e & 7) * 8;
            uint32_t so = (uint32_t)(r * ASTR + c8) * 2;
            cp16(sQh + so, gqh + r * HD + c8);
            cp16(sQl + so, gql + r * HD + c8);
        }
        issue_stage(0, 0);   // commits Q + stage0 together
    }

    // fragment coordinates (validated convention from the GEMM)
    const int a_r = w * 16 + (lane & 7) + ((lane >> 3) & 1) * 8;
    const int a_k = (lane >> 4) * 8;
    const int b_r = (lane & 7) + (lane >> 4) * 8;
    const int b_k = ((lane >> 3) & 1) * 8;

    uint32_t qfh[4][4];
    float m_i[2] = {-1e30f, -1e30f}, l_i[2] = {0.f, 0.f};
    float accO[8][4];
    #pragma unroll
    for (int j = 0; j < 8; j++)
        #pragma unroll
        for (int c = 0; c < 4; c++) accO[j][c] = 0.f;

    for (int t = 0; t < SEQ / 64; t++) {
        if (t + 1 < SEQ / 64) { issue_stage(t + 1, (t + 1) & 1); CP_WAIT(1); }
        else                  { CP_WAIT(0); }
        __syncthreads();

        if (t == 0) {
            #pragma unroll
            for (int ks = 0; ks < 4; ks++)
                ldm_x4(qfh[ks], sQh + (uint32_t)(a_r * ASTR + ks*16 + a_k) * 2);
        }

        const uint32_t sK  = sb + (uint32_t)(2 + 4 * (t & 1)) * ATILE * 2;
        const uint32_t sKl = sK + ATILE * 2;
        const uint32_t sV  = sK + 2 * ATILE * 2;
        const uint32_t sVl = sK + 3 * ATILE * 2;

        // ---- scores: S = Qh Kh^T + Qh Kl^T + Ql Kh^T -------------------
        float accS[8][4];
        #pragma unroll
        for (int j = 0; j < 8; j++)
            #pragma unroll
            for (int c = 0; c < 4; c++) accS[j][c] = 0.f;

        #pragma unroll
        for (int ks = 0; ks < 4; ks++) {
            uint32_t qfl[4], bhf[4][4], blf[4][4];
            ldm_x4(qfl, sQl + (uint32_t)(a_r * ASTR + ks*16 + a_k) * 2);
            #pragma unroll
            for (int n2 = 0; n2 < 4; n2++) {
                ldm_x4(bhf[n2], sK  + (uint32_t)((b_r + n2*16) * ASTR + ks*16 + b_k) * 2);
                ldm_x4(blf[n2], sKl + (uint32_t)((b_r + n2*16) * ASTR + ks*16 + b_k) * 2);
            }
            #pragma unroll
            for (int j = 0; j < 8; j++)
                mma_bf16(accS[j], qfh[ks], &bhf[j >> 1][(j & 1) * 2]);
            #pragma unroll
            for (int j = 0; j < 8; j++)
                mma_bf16(accS[j], qfh[ks], &blf[j >> 1][(j & 1) * 2]);
            #pragma unroll
            for (int j = 0; j < 8; j++)
                mma_bf16(accS[j], qfl, &bhf[j >> 1][(j & 1) * 2]);
        }

        // ---- online softmax (rows er / er+8; row quad = lanes xor 1,2) --
        #pragma unroll
        for (int j = 0; j < 8; j++)
            #pragma unroll
            for (int c = 0; c < 4; c++) accS[j][c] *= 0.125f;

        #pragma unroll
        for (int hh = 0; hh < 2; hh++) {
            float mx = -1e30f;
            #pragma unroll
            for (int j = 0; j < 8; j++)
                mx = fmaxf(mx, fmaxf(accS[j][hh*2], accS[j][hh*2+1]));
            mx = fmaxf(mx, __shfl_xor_sync(0xffffffffu, mx, 1));
            mx = fmaxf(mx, __shfl_xor_sync(0xffffffffu, mx, 2));
            float mn    = fmaxf(m_i[hh], mx);
            float alpha = __expf(m_i[hh] - mn);
            m_i[hh] = mn;
            float sum = 0.f;
            #pragma unroll
            for (int j = 0; j < 8; j++) {
                float p0 = __expf(accS[j][hh*2]   - mn);
                float p1 = __expf(accS[j][hh*2+1] - mn);
                accS[j][hh*2] = p0; accS[j][hh*2+1] = p1;
                sum += p0 + p1;
            }
            sum += __shfl_xor_sync(0xffffffffu, sum, 1);
            sum += __shfl_xor_sync(0xffffffffu, sum, 2);
            l_i[hh] = l_i[hh] * alpha + sum;
            #pragma unroll
            for (int j = 0; j < 8; j++) {
                accO[j][hh*2]   *= alpha;
                accO[j][hh*2+1] *= alpha;
            }
        }

        // ---- P -> A-fragments (D-frag cols == A-frag k-pairs), split ----
        uint32_t pah[4][4], pal[4][4];
        #pragma unroll
        for (int ks = 0; ks < 4; ks++) {
            const int j0 = 2*ks, j1 = j0 + 1;
            #pragma unroll
            for (int q = 0; q < 4; q++) {
                const int jj = (q < 2) ? j0 : j1;
                const int c0 = (q & 1) * 2;
                float v0 = accS[jj][c0], v1 = accS[jj][c0 + 1];
                float h0 = bf16_round(v0), h1 = bf16_round(v1);
                pah[ks][q] = pack_bf16(h0, h1);
                pal[ks][q] = pack_bf16(v0 - h0, v1 - h1);
            }
        }

        // ---- O += Ph Vh + Ph Vl + Pl Vh --------------------------------
        #pragma unroll
        for (int ks = 0; ks < 4; ks++) {
            uint32_t bvh[4][4], bvl[4][4];
            #pragma unroll
            for (int n2 = 0; n2 < 4; n2++) {
                ldm_x4(bvh[n2], sV  + (uint32_t)((b_r + n2*16) * ASTR + ks*16 + b_k) * 2);
                ldm_x4(bvl[n2], sVl + (uint32_t)((b_r + n2*16) * ASTR + ks*16 + b_k) * 2);
            }
            #pragma unroll
            for (int j = 0; j < 8; j++)
                mma_bf16(accO[j], pah[ks], &bvh[j >> 1][(j & 1) * 2]);
            #pragma unroll
            for (int j = 0; j < 8; j++)
                mma_bf16(accO[j], pah[ks], &bvl[j >> 1][(j & 1) * 2]);
            #pragma unroll
            for (int j = 0; j < 8; j++)
                mma_bf16(accO[j], pal[ks], &bvh[j >> 1][(j & 1) * 2]);
        }
        __syncthreads();   // stage consumed; safe for next cp.async overwrite
    }

    // ---- epilogue: normalize, split, write [B,S,DM] bf16 hi/lo ---------
    const int b_  = bh >> 4, hh_ = bh & 15;
    const int er  = lane >> 2, ec = (lane & 3) * 2;
    #pragma unroll
    for (int hh = 0; hh < 2; hh++) {
        const float inv = 1.f / l_i[hh];
        const int m = q0 + w * 16 + er + hh * 8;
        const size_t rowbase = ((size_t)(b_ * SEQ + m)) * DM + hh_ * HD;
        #pragma unroll
        for (int j = 0; j < 8; j++) {
            float o0 = accO[j][hh*2]   * inv;
            float o1 = accO[j][hh*2+1] * inv;
            float h0 = bf16_round(o0), h1 = bf16_round(o1);
            *(uint32_t*)&oh[rowbase + j*8 + ec] = pack_bf16(h0, h1);
            *(uint32_t*)&ol[rowbase + j*8 + ec] = pack_bf16(o0 - h0, o1 - h1);
        }
    }
}

// ---------------------------------------------------------------------------
extern "C" void kernel_launch(void* const* d_in, const int* in_sizes, int n_in,
                              void* d_out, int out_size)
{
    const float* Q  = (const float*)d_in[0];
    const float* K  = (const float*)d_in[1];
    const float* V  = (const float*)d_in[2];
    const float* Wq = (const float*)d_in[3];
    const float* bq = (const float*)d_in[4];
    const float* Wk = (const float*)d_in[5];
    const float* bk = (const float*)d_in[6];
    const float* Wv = (const float*)d_in[7];
    const float* bv = (const float*)d_in[8];
    const float* Wo = (const float*)d_in[9];
    const float* bo = (const float*)d_in[10];
    float* out = (float*)d_out;

    __nv_bfloat16 *ah, *al, *wh, *wl, *qh, *ql, *kh, *kl, *vh, *vl;
    cudaGetSymbolAddress((void**)&ah, g_ah);
    cudaGetSymbolAddress((void**)&al, g_al);
    cudaGetSymbolAddress((void**)&wh, g_wh);
    cudaGetSymbolAddress((void**)&wl, g_wl);
    cudaGetSymbolAddress((void**)&qh, g_qh);
    cudaGetSymbolAddress((void**)&ql, g_ql);
    cudaGetSymbolAddress((void**)&kh, g_kh);
    cudaGetSymbolAddress((void**)&kl, g_kl);
    cudaGetSymbolAddress((void**)&vh, g_vh);
    cudaGetSymbolAddress((void**)&vl, g_vl);

    cudaFuncSetAttribute(gemm_mma_kernel<0>,
                         cudaFuncAttributeMaxDynamicSharedMemorySize, GEMM_SMEM);
    cudaFuncSetAttribute(gemm_mma_kernel<1>,
                         cudaFuncAttributeMaxDynamicSharedMemorySize, GEMM_SMEM);
    cudaFuncSetAttribute(gemm_mma_kernel<2>,
                         cudaFuncAttributeMaxDynamicSharedMemorySize, GEMM_SMEM);
    cudaFuncSetAttribute(attn_mma_kernel,
                         cudaFuncAttributeMaxDynamicSharedMemorySize, ATT_SMEM);

    const dim3 gridSplit(MTOK * DM / 4 / 256);
    const dim3 gridTr(DM / 32, DM / 32), blkTr(32, 8);
    const dim3 gridG(DM / 128, MTOK / 128);

    // Q projection -> split bf16 [B,H,S,Dh]
    split_act_kernel<<<gridSplit, 256>>>(Q, ah, al);
    trans_split_kernel<<<gridTr, blkTr>>>(Wq, wh, wl);
    gemm_mma_kernel<1><<<gridG, 256, GEMM_SMEM>>>(ah, al, wh, wl, bq,
                                                  nullptr, qh, ql);
    // K projection -> split bf16 [B,H,S,Dh]
    split_act_kernel<<<gridSplit, 256>>>(K, ah, al);
    trans_split_kernel<<<gridTr, blkTr>>>(Wk, wh, wl);
    gemm_mma_kernel<1><<<gridG, 256, GEMM_SMEM>>>(ah, al, wh, wl, bk,
                                                  nullptr, kh, kl);
    // V projection -> split bf16 [B,H,Dh,S] (transposed)
    split_act_kernel<<<gridSplit, 256>>>(V, ah, al);
    trans_split_kernel<<<gridTr, blkTr>>>(Wv, wh, wl);
    gemm_mma_kernel<2><<<gridG, 256, GEMM_SMEM>>>(ah, al, wh, wl, bv,
                                                  nullptr, vh, vl);

    // tensor-core attention -> split bf16 [B,S,DM] into ah/al
    const dim3 gridA(SEQ / 64, BATCH * NH);
    attn_mma_kernel<<<gridA, 128, ATT_SMEM>>>(qh, ql, kh, kl, vh, vl, ah, al);

    // output projection -> fp32 d_out
    trans_split_kernel<<<gridTr, blkTr>>>(Wo, wh, wl);
    gemm_mma_kernel<0><<<gridG, 256, GEMM_SMEM>>>(ah, al, wh, wl, bo,
                                                  out, nullptr, nullptr);
}

// round 8
// speedup vs baseline: 3.7609x; 1.0790x over previous
#include <cuda_runtime.h>
#include <cuda_bf16.h>
#include <cstdint>

#define DM   1024
#define NH   16
#define HD   64
#define BATCH 2
#define SEQ  2048
#define MTOK (BATCH*SEQ)   // 4096

// ---------------------------------------------------------------------------
// Scratch (allocation-free rule: __device__ globals)
// ---------------------------------------------------------------------------
static __device__ __nv_bfloat16 g_ah[MTOK*DM];   // activation split hi / attn out hi
static __device__ __nv_bfloat16 g_al[MTOK*DM];   // activation split lo / attn out lo
static __device__ __nv_bfloat16 g_wh[DM*DM];     // W^T split hi  [N,K]
static __device__ __nv_bfloat16 g_wl[DM*DM];     // W^T split lo  [N,K]
static __device__ __nv_bfloat16 g_qh[MTOK*DM];   // q  [B,H,S,Dh]
static __device__ __nv_bfloat16 g_ql[MTOK*DM];
static __device__ __nv_bfloat16 g_kh[MTOK*DM];   // k  [B,H,S,Dh]
static __device__ __nv_bfloat16 g_kl[MTOK*DM];
static __device__ __nv_bfloat16 g_vh[MTOK*DM];   // v  [B,H,Dh,S] (transposed)
static __device__ __nv_bfloat16 g_vl[MTOK*DM];

// ---------------------------------------------------------------------------
// helpers (arch-generic PTX only: ldmatrix / mma.sync / cp.async)
// ---------------------------------------------------------------------------
__device__ __forceinline__ uint32_t smem_u32(const void* p) {
    uint32_t a;
    asm("{ .reg .u64 t; cvta.to.shared.u64 t, %1; cvt.u32.u64 %0, t; }"
        : "=r"(a) : "l"(p));
    return a;
}
__device__ __forceinline__ void ldm_x4(uint32_t* r, uint32_t addr) {
    asm volatile("ldmatrix.sync.aligned.m8n8.x4.shared.b16 {%0,%1,%2,%3}, [%4];"
                 : "=r"(r[0]), "=r"(r[1]), "=r"(r[2]), "=r"(r[3]) : "r"(addr));
}
__device__ __forceinline__ void mma_bf16(float* d, const uint32_t* a,
                                         const uint32_t* b) {
    asm volatile(
        "mma.sync.aligned.m16n8k16.row.col.f32.bf16.bf16.f32 "
        "{%0,%1,%2,%3}, {%4,%5,%6,%7}, {%8,%9}, {%0,%1,%2,%3};"
        : "+f"(d[0]), "+f"(d[1]), "+f"(d[2]), "+f"(d[3])
        : "r"(a[0]), "r"(a[1]), "r"(a[2]), "r"(a[3]), "r"(b[0]), "r"(b[1]));
}
__device__ __forceinline__ void cp16(uint32_t dst, const void* src) {
    asm volatile("cp.async.cg.shared.global [%0], [%1], 16;"
                 :: "r"(dst), "l"(src));
}
#define CP_COMMIT() asm volatile("cp.async.commit_group;" ::: "memory")
#define CP_WAIT(n)  asm volatile("cp.async.wait_group %0;" :: "n"(n) : "memory")

__device__ __forceinline__ uint32_t pack_bf16(float lo, float hi) {
    uint32_t r;
    asm("cvt.rn.bf16x2.f32 %0, %1, %2;" : "=r"(r) : "f"(hi), "f"(lo));
    return r;
}
__device__ __forceinline__ float bf16_round(float v) {
    return __bfloat162float(__float2bfloat16(v));
}

// ---------------------------------------------------------------------------
// Split fp32 activation -> bf16 hi/lo arrays (same [M,K] layout)
// ---------------------------------------------------------------------------
__global__ void __launch_bounds__(256) split_act_kernel(
    const float* __restrict__ x,
    __nv_bfloat16* __restrict__ xh, __nv_bfloat16* __restrict__ xl)
{
    int i = blockIdx.x * blockDim.x + threadIdx.x;   // float4 index
    float4 v = ((const float4*)x)[i];
    float a[4] = {v.x, v.y, v.z, v.w};
    __nv_bfloat162 h01, h23, l01, l23;
    __nv_bfloat16 h0 = __float2bfloat16(a[0]);
    __nv_bfloat16 h1 = __float2bfloat16(a[1]);
    __nv_bfloat16 h2 = __float2bfloat16(a[2]);
    __nv_bfloat16 h3 = __float2bfloat16(a[3]);
    h01.x = h0; h01.y = h1; h23.x = h2; h23.y = h3;
    l01.x = __float2bfloat16(a[0] - __bfloat162float(h0));
    l01.y = __float2bfloat16(a[1] - __bfloat162float(h1));
    l23.x = __float2bfloat16(a[2] - __bfloat162float(h2));
    l23.y = __float2bfloat16(a[3] - __bfloat162float(h3));
    ((__nv_bfloat162*)xh)[2*i]   = h01;
    ((__nv_bfloat162*)xh)[2*i+1] = h23;
    ((__nv_bfloat162*)xl)[2*i]   = l01;
    ((__nv_bfloat162*)xl)[2*i+1] = l23;
}

// ---------------------------------------------------------------------------
// Transpose + split weight:  W[k][n] fp32 -> wh/wl[n][k] bf16
// ---------------------------------------------------------------------------
__global__ void __launch_bounds__(256) trans_split_kernel(
    const float* __restrict__ W,
    __nv_bfloat16* __restrict__ wh, __nv_bfloat16* __restrict__ wl)
{
    __shared__ float t[32][33];
    const int k0 = blockIdx.y * 32, n0 = blockIdx.x * 32;
    const int tx = threadIdx.x, ty = threadIdx.y;     // (32, 8)
    #pragma unroll
    for (int j = 0; j < 4; j++)
        t[ty + j*8][tx] = W[(size_t)(k0 + ty + j*8) * DM + n0 + tx];
    __syncthreads();
    #pragma unroll
    for (int j = 0; j < 4; j++) {
        int nn = ty + j*8;
        float v = t[tx][nn];                           // = W[k0+tx][n0+nn]
        __nv_bfloat16 h = __float2bfloat16(v);
        size_t idx = (size_t)(n0 + nn) * DM + k0 + tx;
        wh[idx] = h;
        wl[idx] = __float2bfloat16(v - __bfloat162float(h));
    }
}

// ---------------------------------------------------------------------------
// Tensor-core split-bf16 GEMM via mma.sync (HMMA).
// MODE 0: fp32 out [M,DM].  MODE 1: split bf16 out [B,H,S,Dh].
// MODE 2: split bf16 out [B,H,Dh,S] via smem-transposed coalesced epilogue.
// ---------------------------------------------------------------------------
#define BM 128
#define BN 128
#define BK 32
#define STR 40
#define TILE_ELEMS (BM * STR)
#define STAGE_ELEMS (4 * TILE_ELEMS)
#define GEMM_SMEM (2 * STAGE_ELEMS * 2)       // 81920 B
#define NCHUNK (DM / BK)                      // 32
#define TSTR 132                              // fp32 transpose stride (MODE 2)

template<int MODE>
__global__ void __launch_bounds__(256) gemm_mma_kernel(
    const __nv_bfloat16* __restrict__ Ah, const __nv_bfloat16* __restrict__ Al,
    const __nv_bfloat16* __restrict__ Bh, const __nv_bfloat16* __restrict__ Bl,
    const float* __restrict__ bias, float* __restrict__ Cf,
    __nv_bfloat16* __restrict__ Ch, __nv_bfloat16* __restrict__ Cl)
{
    extern __shared__ __nv_bfloat16 sm[];
    const uint32_t sbase = smem_u32(sm);

    const int tid  = threadIdx.x;
    const int lane = tid & 31;
    const int wid  = tid >> 5;
    const int wm   = (wid >> 2) * 64;
    const int wn   = (wid & 3) * 32;
    const int bm   = blockIdx.y * BM;
    const int bn   = blockIdx.x * BN;

    float acc[4][4][4];
    #pragma unroll
    for (int i = 0; i < 4; i++)
        #pragma unroll
        for (int j = 0; j < 4; j++)
            #pragma unroll
            for (int c = 0; c < 4; c++) acc[i][j][c] = 0.f;

    const int a_r  = wm + (lane & 7) + ((lane >> 3) & 1) * 8;
    const int a_k  = (lane >> 4) * 8;
    const int b_r  = wn + (lane & 7) + (lane >> 4) * 8;
    const int b_k  = ((lane >> 3) & 1) * 8;

    auto issue_chunk = [&](int c, int stg) {
        const int k0 = c * BK;
        const uint32_t sA = sbase + (uint32_t)(stg * STAGE_ELEMS) * 2;
        #pragma unroll
        for (int i = 0; i < 2; i++) {
            int t = tid + i * 256;
            int r = t >> 2, cc = (t & 3) * 8;
            uint32_t so = (uint32_t)(r * STR + cc) * 2;
            size_t ga = (size_t)(bm + r) * DM + k0 + cc;
            size_t gb = (size_t)(bn + r) * DM + k0 + cc;
            cp16(sA + so,                      Ah + ga);
            cp16(sA + TILE_ELEMS*2 + so,       Al + ga);
            cp16(sA + 2*TILE_ELEMS*2 + so,     Bh + gb);
            cp16(sA + 3*TILE_ELEMS*2 + so,     Bl + gb);
        }
        CP_COMMIT();
    };

    issue_chunk(0, 0);

    for (int c = 0; c < NCHUNK; c++) {
        if (c + 1 < NCHUNK) {
            issue_chunk(c + 1, (c + 1) & 1);
            CP_WAIT(1);
        } else {
            CP_WAIT(0);
        }
        __syncthreads();

        const uint32_t sA  = sbase + (uint32_t)((c & 1) * STAGE_ELEMS) * 2;
        const uint32_t sAl = sA + TILE_ELEMS * 2;
        const uint32_t sB  = sA + 2 * TILE_ELEMS * 2;
        const uint32_t sBl = sA + 3 * TILE_ELEMS * 2;

        #pragma unroll
        for (int ks = 0; ks < BK / 16; ks++) {
            uint32_t ra[4][4], rbh[2][4], rbl[2][4];
            #pragma unroll
            for (int mi = 0; mi < 4; mi++)
                ldm_x4(ra[mi], sA + (uint32_t)((a_r + mi*16) * STR + ks*16 + a_k) * 2);
            #pragma unroll
            for (int n2 = 0; n2 < 2; n2++) {
                ldm_x4(rbh[n2], sB  + (uint32_t)((b_r + n2*16) * STR + ks*16 + b_k) * 2);
                ldm_x4(rbl[n2], sBl + (uint32_t)((b_r + n2*16) * STR + ks*16 + b_k) * 2);
            }
            #pragma unroll
            for (int mi = 0; mi < 4; mi++)
                #pragma unroll
                for (int ni = 0; ni < 4; ni++)
                    mma_bf16(acc[mi][ni], ra[mi], &rbh[ni >> 1][(ni & 1) * 2]);
            #pragma unroll
            for (int mi = 0; mi < 4; mi++)
                #pragma unroll
                for (int ni = 0; ni < 4; ni++)
                    mma_bf16(acc[mi][ni], ra[mi], &rbl[ni >> 1][(ni & 1) * 2]);
            #pragma unroll
            for (int mi = 0; mi < 4; mi++)
                ldm_x4(ra[mi], sAl + (uint32_t)((a_r + mi*16) * STR + ks*16 + a_k) * 2);
            #pragma unroll
            for (int mi = 0; mi < 4; mi++)
                #pragma unroll
                for (int ni = 0; ni < 4; ni++)
                    mma_bf16(acc[mi][ni], ra[mi], &rbh[ni >> 1][(ni & 1) * 2]);
        }
        __syncthreads();
    }

    const int er = lane >> 2;
    const int ec = (lane & 3) * 2;

    if (MODE == 2) {
        // smem-transposed epilogue: coalesced writes to [B,H,Dh,S]
        float* smf = (float*)sm;           // 128 x TSTR fp32 (67584 B < 81920)
        #pragma unroll
        for (int mi = 0; mi < 4; mi++)
            #pragma unroll
            for (int ni = 0; ni < 4; ni++) {
                const int n = wn + ni * 8 + ec;
                const float b0 = bias[bn + n], b1 = bias[bn + n + 1];
                #pragma unroll
                for (int half = 0; half < 2; half++) {
                    const int m = wm + mi * 16 + er + half * 8;
                    smf[(n)     * TSTR + m] = acc[mi][ni][half * 2 + 0] + b0;
                    smf[(n + 1) * TSTR + m] = acc[mi][ni][half * 2 + 1] + b1;
                }
            }
        __syncthreads();
        const int b_ = bm >> 11;
        #pragma unroll
        for (int i = 0; i < 16; i++) {
            const int n  = wid * 16 + i;           // local col 0..127
            const int gn = bn + n;
            const int h  = gn >> 6, d = gn & 63;
            float4 v = *(const float4*)&smf[n * TSTR + lane * 4];
            float h0 = bf16_round(v.x), h1 = bf16_round(v.y);
            float h2 = bf16_round(v.z), h3 = bf16_round(v.w);
            size_t base = (((size_t)b_ * NH + h) * HD + d) * SEQ
                        + (bm & (SEQ - 1)) + lane * 4;
            *(uint32_t*)&Ch[base]     = pack_bf16(h0, h1);
            *(uint32_t*)&Ch[base + 2] = pack_bf16(h2, h3);
            *(uint32_t*)&Cl[base]     = pack_bf16(v.x - h0, v.y - h1);
            *(uint32_t*)&Cl[base + 2] = pack_bf16(v.z - h2, v.w - h3);
        }
        return;
    }

    #pragma unroll
    for (int mi = 0; mi < 4; mi++) {
        #pragma unroll
        for (int ni = 0; ni < 4; ni++) {
            const int n  = bn + wn + ni * 8 + ec;
            const float b0 = bias[n], b1 = bias[n + 1];
            #pragma unroll
            for (int half = 0; half < 2; half++) {
                const int m = bm + wm + mi * 16 + er + half * 8;
                float v0 = acc[mi][ni][half * 2 + 0] + b0;
                float v1 = acc[mi][ni][half * 2 + 1] + b1;
                if (MODE == 0) {
                    float2 o; o.x = v0; o.y = v1;
                    *(float2*)&Cf[(size_t)m * DM + n] = o;
                } else {   // MODE 1
                    float h0 = bf16_round(v0), h1 = bf16_round(v1);
                    const int b_ = m >> 11;
                    const int s  = m & (SEQ - 1);
                    const int h  = n >> 6;
                    const int d  = n & (HD - 1);
                    size_t idx = ((((size_t)b_ * NH + h) * SEQ) + s) * HD + d;
                    *(uint32_t*)&Ch[idx] = pack_bf16(h0, h1);
                    *(uint32_t*)&Cl[idx] = pack_bf16(v0 - h0, v1 - h1);
                }
            }
        }
    }
}

// ---------------------------------------------------------------------------
// Tensor-core flash attention, split bf16 (3-pass per GEMM).
// CTA: 64 queries of one (b,h); 128 thr / 4 warps; warp = 16 rows.
// K double-buffered, V single-buffered (issued post-PV, consumed post-softmax)
// -> 72KB smem -> 3 CTAs/SM. Q hi+lo fragments preloaded once.
// ---------------------------------------------------------------------------
#define ASTR 72
#define ATILE (64 * ASTR)                     // 4608 bf16 elems
// elems: Qh 0 | Ql A | Kh(s) (2+2s)A | Kl(s) (3+2s)A | Vh 6A | Vl 7A
#define ATT_SMEM (8 * ATILE * 2)              // 73728 B

__global__ void __launch_bounds__(128) attn_mma_kernel(
    const __nv_bfloat16* __restrict__ qh, const __nv_bfloat16* __restrict__ ql,
    const __nv_bfloat16* __restrict__ kh, const __nv_bfloat16* __restrict__ kl,
    const __nv_bfloat16* __restrict__ vh, const __nv_bfloat16* __restrict__ vl,
    __nv_bfloat16* __restrict__ oh, __nv_bfloat16* __restrict__ ol)
{
    extern __shared__ __nv_bfloat16 smA[];
    const uint32_t sb  = smem_u32(smA);
    const int tid  = threadIdx.x;
    const int lane = tid & 31;
    const int w    = tid >> 5;
    const int bh   = blockIdx.y;              // b*NH + h
    const int q0   = blockIdx.x * 64;
    const size_t bo = (size_t)bh * SEQ * HD;

    const uint32_t sQh = sb;
    const uint32_t sQl = sb + ATILE * 2;
    const uint32_t sVh = sb + 6 * ATILE * 2;
    const uint32_t sVl = sb + 7 * ATILE * 2;

    auto issue_K = [&](int t, int stg) {      // no commit
        const int c0 = t * 64;
        const uint32_t base = sb + (uint32_t)(2 + 2 * stg) * ATILE * 2;
        const __nv_bfloat16* gkh = kh + bo + (size_t)c0 * HD;
        const __nv_bfloat16* gkl = kl + bo + (size_t)c0 * HD;
        #pragma unroll
        for (int i = 0; i < 4; i++) {
            int e = tid + i * 128;
            int r = e >> 3, c8 = (e & 7) * 8;
            uint32_t so = (uint32_t)(r * ASTR + c8) * 2;
            cp16(base + so,             gkh + r * HD + c8);
            cp16(base + ATILE*2 + so,   gkl + r * HD + c8);
        }
    };
    auto issue_V = [&](int t) {               // no commit
        const int c0 = t * 64;
        const __nv_bfloat16* gvh = vh + bo + c0;
        const __nv_bfloat16* gvl = vl + bo + c0;
        #pragma unroll
        for (int i = 0; i < 4; i++) {
            int e = tid + i * 128;
            int r = e >> 3, c8 = (e & 7) * 8;   // r = d row, c8 = key col
            uint32_t so = (uint32_t)(r * ASTR + c8) * 2;
            cp16(sVh + so, gvh + (size_t)r * SEQ + c8);
            cp16(sVl + so, gvl + (size_t)r * SEQ + c8);
        }
    };

    // prologue: G0 = {Q, K0}, G1 = {V0}
    {
        const __nv_bfloat16* gqh = qh + bo + (size_t)q0 * HD;
        const __nv_bfloat16* gql = ql + bo + (size_t)q0 * HD;
        #pragma unroll
        for (int i = 0; i < 4; i++) {
            int e = tid + i * 128;
            int r = e >> 3, c8 = (e & 7) * 8;
            uint32_t so = (uint32_t)(r * ASTR + c8) * 2;
            cp16(sQh + so, gqh + r * HD + c8);
            cp16(sQl + so, gql + r * HD + c8);
        }
        issue_K(0, 0);
        CP_COMMIT();
        issue_V(0);
        CP_COMMIT();
    }

    const int a_r = w * 16 + (lane & 7) + ((lane >> 3) & 1) * 8;
    const int a_k = (lane >> 4) * 8;
    const int b_r = (lane & 7) + (lane >> 4) * 8;
    const int b_k = ((lane >> 3) & 1) * 8;

    uint32_t qfh[4][4], qfl[4][4];
    float m_i[2] = {-1e30f, -1e30f}, l_i[2] = {0.f, 0.f};
    float accO[8][4];
    #pragma unroll
    for (int j = 0; j < 8; j++)
        #pragma unroll
        for (int c = 0; c < 4; c++) accO[j][c] = 0.f;

    for (int t = 0; t < SEQ / 64; t++) {
        // 1. prefetch K(t+1) into the other stage (its last reads ended tile t-1)
        if (t + 1 < SEQ / 64) { issue_K(t + 1, (t + 1) & 1); CP_COMMIT(); }
        // 2. wait K(t): pending = {V(t), K(t+1)} or {V(t)} on last tile
        if (t + 1 < SEQ / 64) { CP_WAIT(2); } else { CP_WAIT(1); }
        __syncthreads();                       // sync_K

        if (t == 0) {
            #pragma unroll
            for (int ks = 0; ks < 4; ks++) {
                ldm_x4(qfh[ks], sQh + (uint32_t)(a_r * ASTR + ks*16 + a_k) * 2);
                ldm_x4(qfl[ks], sQl + (uint32_t)(a_r * ASTR + ks*16 + a_k) * 2);
            }
        }

        const uint32_t sK  = sb + (uint32_t)(2 + 2 * (t & 1)) * ATILE * 2;
        const uint32_t sKl = sK + ATILE * 2;

        // ---- scores: S = Qh Kh^T + Qh Kl^T + Ql Kh^T -------------------
        float accS[8][4];
        #pragma unroll
        for (int j = 0; j < 8; j++)
            #pragma unroll
            for (int c = 0; c < 4; c++) accS[j][c] = 0.f;

        #pragma unroll
        for (int ks = 0; ks < 4; ks++) {
            uint32_t bhf[4][4], blf[4][4];
            #pragma unroll
            for (int n2 = 0; n2 < 4; n2++) {
                ldm_x4(bhf[n2], sK  + (uint32_t)((b_r + n2*16) * ASTR + ks*16 + b_k) * 2);
                ldm_x4(blf[n2], sKl + (uint32_t)((b_r + n2*16) * ASTR + ks*16 + b_k) * 2);
            }
            #pragma unroll
            for (int j = 0; j < 8; j++)
                mma_bf16(accS[j], qfh[ks], &bhf[j >> 1][(j & 1) * 2]);
            #pragma unroll
            for (int j = 0; j < 8; j++)
                mma_bf16(accS[j], qfh[ks], &blf[j >> 1][(j & 1) * 2]);
            #pragma unroll
            for (int j = 0; j < 8; j++)
                mma_bf16(accS[j], qfl[ks], &bhf[j >> 1][(j & 1) * 2]);
        }

        // ---- online softmax, both row-halves phase-parallel ------------
        #pragma unroll
        for (int j = 0; j < 8; j++)
            #pragma unroll
            for (int c = 0; c < 4; c++) accS[j][c] *= 0.125f;

        float mx0 = -1e30f, mx1 = -1e30f;
        #pragma unroll
        for (int j = 0; j < 8; j++) {
            mx0 = fmaxf(mx0, fmaxf(accS[j][0], accS[j][1]));
            mx1 = fmaxf(mx1, fmaxf(accS[j][2], accS[j][3]));
        }
        mx0 = fmaxf(mx0, __shfl_xor_sync(0xffffffffu, mx0, 1));
        mx1 = fmaxf(mx1, __shfl_xor_sync(0xffffffffu, mx1, 1));
        mx0 = fmaxf(mx0, __shfl_xor_sync(0xffffffffu, mx0, 2));
        mx1 = fmaxf(mx1, __shfl_xor_sync(0xffffffffu, mx1, 2));
        const float mn0 = fmaxf(m_i[0], mx0), mn1 = fmaxf(m_i[1], mx1);
        const float al0 = __expf(m_i[0] - mn0), al1 = __expf(m_i[1] - mn1);
        m_i[0] = mn0; m_i[1] = mn1;
        float s0 = 0.f, s1 = 0.f;
        #pragma unroll
        for (int j = 0; j < 8; j++) {
            float p0 = __expf(accS[j][0] - mn0);
            float p1 = __expf(accS[j][1] - mn0);
            float p2 = __expf(accS[j][2] - mn1);
            float p3 = __expf(accS[j][3] - mn1);
            accS[j][0] = p0; accS[j][1] = p1; accS[j][2] = p2; accS[j][3] = p3;
            s0 += p0 + p1; s1 += p2 + p3;
        }
        s0 += __shfl_xor_sync(0xffffffffu, s0, 1);
        s1 += __shfl_xor_sync(0xffffffffu, s1, 1);
        s0 += __shfl_xor_sync(0xffffffffu, s0, 2);
        s1 += __shfl_xor_sync(0xffffffffu, s1, 2);
        l_i[0] = l_i[0] * al0 + s0;
        l_i[1] = l_i[1] * al1 + s1;
        #pragma unroll
        for (int j = 0; j < 8; j++) {
            accO[j][0] *= al0; accO[j][1] *= al0;
            accO[j][2] *= al1; accO[j][3] *= al1;
        }

        // ---- P -> A-fragments, split bf16 ------------------------------
        uint32_t pah[4][4], pal[4][4];
        #pragma unroll
        for (int ks = 0; ks < 4; ks++) {
            const int j0 = 2*ks, j1 = j0 + 1;
            #pragma unroll
            for (int q = 0; q < 4; q++) {
                const int jj = (q < 2) ? j0 : j1;
                const int c0 = (q & 1) * 2;
                float v0 = accS[jj][c0], v1 = accS[jj][c0 + 1];
                float h0 = bf16_round(v0), h1 = bf16_round(v1);
                pah[ks][q] = pack_bf16(h0, h1);
                pal[ks][q] = pack_bf16(v0 - h0, v1 - h1);
            }
        }

        // 5. wait V(t): pending = {K(t+1)} or {} ----------------------------
        if (t + 1 < SEQ / 64) { CP_WAIT(1); } else { CP_WAIT(0); }
        __syncthreads();                       // sync_V

        // ---- O += Ph Vh + Ph Vl + Pl Vh --------------------------------
        #pragma unroll
        for (int ks = 0; ks < 4; ks++) {
            uint32_t bvh[4][4], bvl[4][4];
            #pragma unroll
            for (int n2 = 0; n2 < 4; n2++) {
                ldm_x4(bvh[n2], sVh + (uint32_t)((b_r + n2*16) * ASTR + ks*16 + b_k) * 2);
                ldm_x4(bvl[n2], sVl + (uint32_t)((b_r + n2*16) * ASTR + ks*16 + b_k) * 2);
            }
            #pragma unroll
            for (int j = 0; j < 8; j++)
                mma_bf16(accO[j], pah[ks], &bvh[j >> 1][(j & 1) * 2]);
            #pragma unroll
            for (int j = 0; j < 8; j++)
                mma_bf16(accO[j], pah[ks], &bvl[j >> 1][(j & 1) * 2]);
            #pragma unroll
            for (int j = 0; j < 8; j++)
                mma_bf16(accO[j], pal[ks], &bvh[j >> 1][(j & 1) * 2]);
        }
        __syncthreads();                       // sync_end: V reads done

        // 9. prefetch V(t+1) into the (single) V buffer
        if (t + 1 < SEQ / 64) { issue_V(t + 1); CP_COMMIT(); }
    }

    // ---- epilogue: normalize, split, write [B,S,DM] bf16 hi/lo ---------
    const int b_  = bh >> 4, hh_ = bh & 15;
    const int er  = lane >> 2, ec = (lane & 3) * 2;
    #pragma unroll
    for (int hh = 0; hh < 2; hh++) {
        const float inv = 1.f / l_i[hh];
        const int m = q0 + w * 16 + er + hh * 8;
        const size_t rowbase = ((size_t)(b_ * SEQ + m)) * DM + hh_ * HD;
        #pragma unroll
        for (int j = 0; j < 8; j++) {
            float o0 = accO[j][hh*2]   * inv;
            float o1 = accO[j][hh*2+1] * inv;
            float h0 = bf16_round(o0), h1 = bf16_round(o1);
            *(uint32_t*)&oh[rowbase + j*8 + ec] = pack_bf16(h0, h1);
            *(uint32_t*)&ol[rowbase + j*8 + ec] = pack_bf16(o0 - h0, o1 - h1);
        }
    }
}

// ---------------------------------------------------------------------------
extern "C" void kernel_launch(void* const* d_in, const int* in_sizes, int n_in,
                              void* d_out, int out_size)
{
    const float* Q  = (const float*)d_in[0];
    const float* K  = (const float*)d_in[1];
    const float* V  = (const float*)d_in[2];
    const float* Wq = (const float*)d_in[3];
    const float* bq = (const float*)d_in[4];
    const float* Wk = (const float*)d_in[5];
    const float* bk = (const float*)d_in[6];
    const float* Wv = (const float*)d_in[7];
    const float* bv = (const float*)d_in[8];
    const float* Wo = (const float*)d_in[9];
    const float* bo = (const float*)d_in[10];
    float* out = (float*)d_out;

    __nv_bfloat16 *ah, *al, *wh, *wl, *qh, *ql, *kh, *kl, *vh, *vl;
    cudaGetSymbolAddress((void**)&ah, g_ah);
    cudaGetSymbolAddress((void**)&al, g_al);
    cudaGetSymbolAddress((void**)&wh, g_wh);
    cudaGetSymbolAddress((void**)&wl, g_wl);
    cudaGetSymbolAddress((void**)&qh, g_qh);
    cudaGetSymbolAddress((void**)&ql, g_ql);
    cudaGetSymbolAddress((void**)&kh, g_kh);
    cudaGetSymbolAddress((void**)&kl, g_kl);
    cudaGetSymbolAddress((void**)&vh, g_vh);
    cudaGetSymbolAddress((void**)&vl, g_vl);

    cudaFuncSetAttribute(gemm_mma_kernel<0>,
                         cudaFuncAttributeMaxDynamicSharedMemorySize, GEMM_SMEM);
    cudaFuncSetAttribute(gemm_mma_kernel<1>,
                         cudaFuncAttributeMaxDynamicSharedMemorySize, GEMM_SMEM);
    cudaFuncSetAttribute(gemm_mma_kernel<2>,
                         cudaFuncAttributeMaxDynamicSharedMemorySize, GEMM_SMEM);
    cudaFuncSetAttribute(attn_mma_kernel,
                         cudaFuncAttributeMaxDynamicSharedMemorySize, ATT_SMEM);

    const dim3 gridSplit(MTOK * DM / 4 / 256);
    const dim3 gridTr(DM / 32, DM / 32), blkTr(32, 8);
    const dim3 gridG(DM / 128, MTOK / 128);

    // Q projection -> split bf16 [B,H,S,Dh]
    split_act_kernel<<<gridSplit, 256>>>(Q, ah, al);
    trans_split_kernel<<<gridTr, blkTr>>>(Wq, wh, wl);
    gemm_mma_kernel<1><<<gridG, 256, GEMM_SMEM>>>(ah, al, wh, wl, bq,
                                                  nullptr, qh, ql);
    // K projection -> split bf16 [B,H,S,Dh]
    split_act_kernel<<<gridSplit, 256>>>(K, ah, al);
    trans_split_kernel<<<gridTr, blkTr>>>(Wk, wh, wl);
    gemm_mma_kernel<1><<<gridG, 256, GEMM_SMEM>>>(ah, al, wh, wl, bk,
                                                  nullptr, kh, kl);
    // V projection -> split bf16 [B,H,Dh,S] (transposed, coalesced epilogue)
    split_act_kernel<<<gridSplit, 256>>>(V, ah, al);
    trans_split_kernel<<<gridTr, blkTr>>>(Wv, wh, wl);
    gemm_mma_kernel<2><<<gridG, 256, GEMM_SMEM>>>(ah, al, wh, wl, bv,
                                                  nullptr, vh, vl);

    // tensor-core attention -> split bf16 [B,S,DM] into ah/al
    const dim3 gridA(SEQ / 64, BATCH * NH);
    attn_mma_kernel<<<gridA, 128, ATT_SMEM>>>(qh, ql, kh, kl, vh, vl, ah, al);

    // output projection -> fp32 d_out
    trans_split_kernel<<<gridTr, blkTr>>>(Wo, wh, wl);
    gemm_mma_kernel<0><<<gridG, 256, GEMM_SMEM>>>(ah, al, wh, wl, bo,
                                                  out, nullptr, nullptr);
}